// round 4
// baseline (speedup 1.0000x reference)
#include <cuda_runtime.h>
#include <math.h>

#define BB   8
#define TT   100
#define MTOT 800
#define HH   1024
#define LL   512
#define VV   32000
#define V4   (VV / 4)      // 8000

// GEMM tiling: 128x256 CTA tile, 8 warps (2m x 4n), warp tile 64x64
#define BM 128
#define BN 256
#define BK 16
#define NK (HH / BK)       // 64
#define GT 256

#define A_PITCH 20
#define B_PITCH 264
#define A_STAGE (BM * A_PITCH)          // 2560 floats
#define B_STAGE (BK * B_PITCH)          // 4224 floats
#define SMEM_FLOATS (2 * A_STAGE + 2 * B_STAGE)
#define SMEM_BYTES (SMEM_FLOATS * 4)    // 54272 B

// Scratch (no cudaMalloc allowed)
__device__ float g_logits[(size_t)MTOT * VV];   // 102.4 MB
__device__ float g_pgen[MTOT];
__device__ float g_rsum[MTOT];   // sum of exp(logit) per row (no max shift)
__device__ float g_C[MTOT];      // log(p_gen / rsum)

// ---------------------------------------------------------------------------
// cp.async helpers
// ---------------------------------------------------------------------------
__device__ __forceinline__ void cp_async16(float* smem_dst, const float* gsrc) {
    unsigned saddr = (unsigned)__cvta_generic_to_shared(smem_dst);
    asm volatile("cp.async.cg.shared.global [%0], [%1], 16;\n" ::"r"(saddr), "l"(gsrc));
}
__device__ __forceinline__ void cp_async_commit() {
    asm volatile("cp.async.commit_group;\n");
}
template <int N>
__device__ __forceinline__ void cp_async_wait() {
    asm volatile("cp.async.wait_group %0;\n" ::"n"(N));
}

// ---------------------------------------------------------------------------
// Kernel 1: p_gen[row] = sigmoid(dot(x[row], w_gen) + b_gen); also zero g_rsum
// ---------------------------------------------------------------------------
__global__ void pgen_kernel(const float* __restrict__ x,
                            const float* __restrict__ w_gen,
                            const float* __restrict__ b_gen) {
    int row = blockIdx.x;
    if (threadIdx.x == 0) g_rsum[row] = 0.f;
    const float4* xr = (const float4*)(x + (size_t)row * HH);
    const float4* wr = (const float4*)w_gen;
    float s = 0.f;
    for (int i = threadIdx.x; i < HH / 4; i += 256) {
        float4 a = xr[i], b = wr[i];
        s += a.x * b.x + a.y * b.y + a.z * b.z + a.w * b.w;
    }
    __shared__ float red[256];
    red[threadIdx.x] = s;
    __syncthreads();
    for (int off = 128; off > 0; off >>= 1) {
        if (threadIdx.x < off) red[threadIdx.x] += red[threadIdx.x + off];
        __syncthreads();
    }
    if (threadIdx.x == 0) {
        float z = red[0] + b_gen[0];
        g_pgen[row] = 1.f / (1.f + expf(-z));
    }
}

// ---------------------------------------------------------------------------
// Kernel 2: tf32 GEMM 128x256 tile, warp tile 64x64, cp.async double buffer.
// Epilogue: write logits (+bias) AND accumulate per-row sum of exp(logit).
// Grid: (m-tiles=7, n-tiles=125), m fastest => W slice reused via L2.
// ---------------------------------------------------------------------------
__global__ __launch_bounds__(GT)
void gemm_tf32(const float* __restrict__ A,
               const float* __restrict__ W,
               const float* __restrict__ bias) {
    extern __shared__ float smem[];
    float* As = smem;                 // [2][BM][A_PITCH]
    float* Bs = smem + 2 * A_STAGE;   // [2][BK][B_PITCH]

    const int tid   = threadIdx.x;
    const int lane  = tid & 31;
    const int warp  = tid >> 5;
    const int warpM = warp & 1;       // 0..1 (64 rows each)
    const int warpN = warp >> 1;      // 0..3 (64 cols each)
    const int g     = lane >> 2;      // 0..7
    const int t     = lane & 3;       // 0..3
    const int m0    = blockIdx.x * BM;
    const int n0    = blockIdx.y * BN;

    float acc[4][8][4];
#pragma unroll
    for (int i = 0; i < 4; i++)
#pragma unroll
        for (int j = 0; j < 8; j++)
#pragma unroll
            for (int k = 0; k < 4; k++) acc[i][j][k] = 0.f;

    // A tile: 128x16 = 512 float4, 2 per thread. B tile: 16x256 = 1024 float4, 4/thread.
    const int ar0 = tid >> 2,         ac0 = (tid & 3) * 4;
    const int ar1 = (tid + 256) >> 2, ac1 = ((tid + 256) & 3) * 4;
    const int garow0 = (m0 + ar0 < MTOT) ? (m0 + ar0) : (MTOT - 1);
    const int garow1 = (m0 + ar1 < MTOT) ? (m0 + ar1) : (MTOT - 1);

    // prefetch stage 0
    {
        cp_async16(As + ar0 * A_PITCH + ac0, A + (size_t)garow0 * HH + ac0);
        cp_async16(As + ar1 * A_PITCH + ac1, A + (size_t)garow1 * HH + ac1);
#pragma unroll
        for (int i = 0; i < 4; i++) {
            int s  = tid + i * 256;
            int kk = s >> 6;
            int c  = (s & 63) * 4;
            cp_async16(Bs + kk * B_PITCH + c, W + (size_t)kk * VV + n0 + c);
        }
        cp_async_commit();
    }

    for (int k0 = 0; k0 < NK; k0++) {
        const int cur = k0 & 1;
        const int nxt = cur ^ 1;
        if (k0 + 1 < NK) {
            const int kg = (k0 + 1) * BK;
            cp_async16(As + nxt * A_STAGE + ar0 * A_PITCH + ac0,
                       A + (size_t)garow0 * HH + kg + ac0);
            cp_async16(As + nxt * A_STAGE + ar1 * A_PITCH + ac1,
                       A + (size_t)garow1 * HH + kg + ac1);
#pragma unroll
            for (int i = 0; i < 4; i++) {
                int s  = tid + i * 256;
                int kk = s >> 6;
                int c  = (s & 63) * 4;
                cp_async16(Bs + nxt * B_STAGE + kk * B_PITCH + c,
                           W + (size_t)(kg + kk) * VV + n0 + c);
            }
            cp_async_commit();
            cp_async_wait<1>();
        } else {
            cp_async_wait<0>();
        }
        __syncthreads();

        const float* Ab = As + cur * A_STAGE + (warpM * 64) * A_PITCH;
        const float* Bb = Bs + cur * B_STAGE + warpN * 64;

#pragma unroll
        for (int kk = 0; kk < BK; kk += 8) {
            unsigned a[4][4], b[8][2];
#pragma unroll
            for (int mi = 0; mi < 4; mi++) {
                const float* ap = Ab + (mi * 16 + g) * A_PITCH + kk + t;
                a[mi][0] = __float_as_uint(ap[0]);
                a[mi][1] = __float_as_uint(ap[8 * A_PITCH]);
                a[mi][2] = __float_as_uint(ap[4]);
                a[mi][3] = __float_as_uint(ap[8 * A_PITCH + 4]);
            }
#pragma unroll
            for (int ni = 0; ni < 8; ni++) {
                const float* bp = Bb + (kk + t) * B_PITCH + ni * 8 + g;
                b[ni][0] = __float_as_uint(bp[0]);
                b[ni][1] = __float_as_uint(bp[4 * B_PITCH]);
            }
#pragma unroll
            for (int mi = 0; mi < 4; mi++)
#pragma unroll
                for (int ni = 0; ni < 8; ni++) {
                    asm volatile(
                        "mma.sync.aligned.m16n8k8.row.col.f32.tf32.tf32.f32 "
                        "{%0,%1,%2,%3}, {%4,%5,%6,%7}, {%8,%9}, {%0,%1,%2,%3};"
                        : "+f"(acc[mi][ni][0]), "+f"(acc[mi][ni][1]),
                          "+f"(acc[mi][ni][2]), "+f"(acc[mi][ni][3])
                        : "r"(a[mi][0]), "r"(a[mi][1]), "r"(a[mi][2]), "r"(a[mi][3]),
                          "r"(b[ni][0]), "r"(b[ni][1]));
                }
        }
        __syncthreads();
    }

    // Epilogue: bias + write logits + per-row sum of exp
    float psum_lo[4] = {0.f, 0.f, 0.f, 0.f};
    float psum_hi[4] = {0.f, 0.f, 0.f, 0.f};
#pragma unroll
    for (int ni = 0; ni < 8; ni++) {
        int c = n0 + warpN * 64 + ni * 8 + 2 * t;
        float2 bb = *reinterpret_cast<const float2*>(bias + c);
#pragma unroll
        for (int mi = 0; mi < 4; mi++) {
            int r = m0 + warpM * 64 + mi * 16 + g;
            float l0 = acc[mi][ni][0] + bb.x, l1 = acc[mi][ni][1] + bb.y;
            float l2 = acc[mi][ni][2] + bb.x, l3 = acc[mi][ni][3] + bb.y;
            if (r < MTOT) {
                *reinterpret_cast<float2*>(g_logits + (size_t)r * VV + c) =
                    make_float2(l0, l1);
                psum_lo[mi] += __expf(l0) + __expf(l1);
            }
            if (r + 8 < MTOT) {
                *reinterpret_cast<float2*>(g_logits + (size_t)(r + 8) * VV + c) =
                    make_float2(l2, l3);
                psum_hi[mi] += __expf(l2) + __expf(l3);
            }
        }
    }
    __syncthreads();
    float* srow = smem;  // reuse as [BM] row partials
    if (tid < BM) srow[tid] = 0.f;
    __syncthreads();
#pragma unroll
    for (int mi = 0; mi < 4; mi++) {
        atomicAdd(&srow[warpM * 64 + mi * 16 + g], psum_lo[mi]);
        atomicAdd(&srow[warpM * 64 + mi * 16 + 8 + g], psum_hi[mi]);
    }
    __syncthreads();
    if (tid < BM && m0 + tid < MTOT) atomicAdd(&g_rsum[m0 + tid], srow[tid]);
}

// ---------------------------------------------------------------------------
// Kernel 3: g_C[r] = log(p_gen / sum_exp)
// ---------------------------------------------------------------------------
__global__ void prep_kernel() {
    int r = blockIdx.x * 256 + threadIdx.x;
    if (r < MTOT) g_C[r] = logf(g_pgen[r] / g_rsum[r]);
}

// ---------------------------------------------------------------------------
// Kernel 4: dense pass — out[row, v] = logit[row, v] + C[row]
//   (equals log of the generation part; copy-touched slots fixed up after)
// ---------------------------------------------------------------------------
__global__ void dense_kernel(float* __restrict__ out) {
    int row = blockIdx.y;
    float C = g_C[row];
    const float4* l4 = (const float4*)(g_logits + (size_t)row * VV);
    float4* o4 = (float4*)(out + (size_t)row * VV);
    int j = blockIdx.x * 256 + threadIdx.x;
#pragma unroll
    for (int k = 0; k < 4; k++) {
        int i = j + k * 2048;
        if (i < V4) {
            float4 l = l4[i];
            l.x += C; l.y += C; l.z += C; l.w += C;
            o4[i] = l;
        }
    }
}

// ---------------------------------------------------------------------------
// Kernel 5: sparse fixup — for each copy-touched slot:
//   out[row, idx] = log( copy_total(idx) + exp(out[row, idx]) )
// Duplicate indices within the row are merged by a leader scan in smem.
// ---------------------------------------------------------------------------
__global__ void fixup_kernel(const float* __restrict__ attn,
                             const int* __restrict__ enc,
                             float* __restrict__ out) {
    int row = blockIdx.x;
    int b   = row / TT;
    const float* ar = attn + (size_t)row * LL;

    __shared__ float av[LL];
    __shared__ float sval[LL];
    __shared__ int   sidx[LL];
    __shared__ float red[128];

    int tid = threadIdx.x;  // 128 threads

    float m = -1e30f;
    for (int l = tid; l < LL; l += 128) {
        float a = ar[l];
        av[l] = a;
        m = fmaxf(m, a);
    }
    red[tid] = m;
    __syncthreads();
    for (int off = 64; off > 0; off >>= 1) {
        if (tid < off) red[tid] = fmaxf(red[tid], red[tid + off]);
        __syncthreads();
    }
    m = red[0];
    __syncthreads();

    float s = 0.f;
    for (int l = tid; l < LL; l += 128) s += __expf(av[l] - m);
    red[tid] = s;
    __syncthreads();
    for (int off = 64; off > 0; off >>= 1) {
        if (tid < off) red[tid] += red[tid + off];
        __syncthreads();
    }
    s = red[0];

    float scale = (1.f - g_pgen[row]) / s;
    for (int l = tid; l < LL; l += 128) {
        sval[l] = scale * __expf(av[l] - m);
        sidx[l] = enc[b * LL + l];
    }
    __syncthreads();

    for (int l = tid; l < LL; l += 128) {
        int id = sidx[l];
        bool leader = true;
        for (int j = 0; j < l; j++)
            if (sidx[j] == id) { leader = false; break; }
        if (leader) {
            float c = sval[l];
            for (int j = l + 1; j < LL; j++)
                if (sidx[j] == id) c += sval[j];
            size_t o = (size_t)row * VV + id;
            out[o] = logf(c + __expf(out[o]));
        }
    }
}

// ---------------------------------------------------------------------------
extern "C" void kernel_launch(void* const* d_in, const int* in_sizes, int n_in,
                              void* d_out, int out_size) {
    const float* x    = (const float*)d_in[0];  // [8,100,1024]
    const float* attn = (const float*)d_in[1];  // [8,100,512]
    const int*   enc  = (const int*)  d_in[2];  // [8,512]
    const float* Wv   = (const float*)d_in[3];  // [1024,32000]
    const float* bv   = (const float*)d_in[4];  // [32000]
    const float* wg   = (const float*)d_in[5];  // [1024,1]
    const float* bg   = (const float*)d_in[6];  // [1]
    float* out = (float*)d_out;                 // [8,100,32000]

    static bool attr_set = false;
    if (!attr_set) {
        cudaFuncSetAttribute(gemm_tf32, cudaFuncAttributeMaxDynamicSharedMemorySize,
                             SMEM_BYTES);
        attr_set = true;
    }

    pgen_kernel<<<MTOT, 256>>>(x, wg, bg);

    dim3 ggrid((MTOT + BM - 1) / BM, VV / BN);  // (7, 125), m-tile fastest
    gemm_tf32<<<ggrid, GT, SMEM_BYTES>>>(x, Wv, bv);

    prep_kernel<<<4, 256>>>();

    dim3 dgrid(8, MTOT);                        // 8*256*4 = 8192 >= V4
    dense_kernel<<<dgrid, 256>>>(out);

    fixup_kernel<<<MTOT, 128>>>(attn, enc, out);
}

// round 6
// speedup vs baseline: 1.0910x; 1.0910x over previous
#include <cuda_runtime.h>
#include <cuda_bf16.h>
#include <math.h>
#include <stdint.h>

#define BB   8
#define TT   100
#define MTOT 800
#define HH   1024
#define LL   512
#define VV   32000
#define V4   (VV / 4)

// bf16 GEMM tiling: 128x256 CTA tile, 8 warps (2m x 4n), warp tile 64x64
#define BM 128
#define BN 256
#define BK 32
#define NCH (HH / BK)      // 32
#define GT 256
#define STAGES 3

// smem: bias [0,1024), then 3 stages of (A 10240 + B 20480)
#define APITCH_W 20                         // words (40 bf16, 80 B)
#define A_BYTES (BM * 80)                   // 10240
#define B_BYTES (BN * 80)                   // 20480
#define STAGE_BYTES (A_BYTES + B_BYTES)     // 30720
#define SM_BIAS 0
#define SM_ST0  1024
#define SM_TOTAL (SM_ST0 + STAGES * STAGE_BYTES)   // 93184

// Scratch (no cudaMalloc allowed)
__device__ float g_logits[(size_t)MTOT * VV];          // 102.4 MB
__device__ __nv_bfloat16 g_xb[(size_t)MTOT * HH];      // 1.6 MB
__device__ __nv_bfloat16 g_wt[(size_t)VV * HH];        // 65.5 MB (W transposed)
__device__ float g_pgen[MTOT];
__device__ float g_rsum[MTOT];
__device__ float g_C[MTOT];

// ---------------------------------------------------------------------------
__device__ __forceinline__ void cp_async16(uint32_t saddr, const void* gsrc) {
    asm volatile("cp.async.cg.shared.global [%0], [%1], 16;\n" ::"r"(saddr), "l"(gsrc));
}
__device__ __forceinline__ void cp_commit() { asm volatile("cp.async.commit_group;\n"); }
template <int N>
__device__ __forceinline__ void cp_wait() {
    asm volatile("cp.async.wait_group %0;\n" ::"n"(N));
}

// ---------------------------------------------------------------------------
// Kernel 0a: convert x -> bf16 (k-contiguous already)
// ---------------------------------------------------------------------------
__global__ void convx_kernel(const float* __restrict__ x) {
    int i = blockIdx.x * 256 + threadIdx.x;       // over float4, 204800 total
    const float4* x4 = (const float4*)x;
    if (i < MTOT * HH / 4) {
        float4 v = x4[i];
        __nv_bfloat162* o = (__nv_bfloat162*)g_xb + i * 2;
        o[0] = __floats2bfloat162_rn(v.x, v.y);
        o[1] = __floats2bfloat162_rn(v.z, v.w);
    }
}

// ---------------------------------------------------------------------------
// Kernel 0b: transpose + convert W[1024][32000] f32 -> g_wt[32000][1024] bf16
// 64x64 tiles, smem staging.
// ---------------------------------------------------------------------------
__global__ void transw_kernel(const float* __restrict__ W) {
    __shared__ float tile[64][65];
    int n0 = blockIdx.x * 64;       // vocab dim
    int k0 = blockIdx.y * 64;       // hidden dim
    int tid = threadIdx.x;
    // read: rows k (coalesced over n)
#pragma unroll
    for (int i = 0; i < 16; i++) {
        int s = tid + i * 256;
        int r = s >> 6, c = s & 63;
        tile[r][c] = W[(size_t)(k0 + r) * VV + n0 + c];
    }
    __syncthreads();
    // write: rows n, k contiguous as bf16x2
#pragma unroll
    for (int i = 0; i < 8; i++) {
        int s = tid + i * 256;
        int nr = s >> 5, kp = s & 31;
        __nv_bfloat162 v = __floats2bfloat162_rn(tile[2 * kp][nr], tile[2 * kp + 1][nr]);
        *(__nv_bfloat162*)(g_wt + (size_t)(n0 + nr) * HH + k0 + 2 * kp) = v;
    }
}

// ---------------------------------------------------------------------------
// Kernel 1: p_gen (fp32) + zero rsum
// ---------------------------------------------------------------------------
__global__ void pgen_kernel(const float* __restrict__ x,
                            const float* __restrict__ w_gen,
                            const float* __restrict__ b_gen) {
    int row = blockIdx.x;
    if (threadIdx.x == 0) g_rsum[row] = 0.f;
    const float4* xr = (const float4*)(x + (size_t)row * HH);
    const float4* wr = (const float4*)w_gen;
    float s = 0.f;
    for (int i = threadIdx.x; i < HH / 4; i += 256) {
        float4 a = xr[i], b = wr[i];
        s += a.x * b.x + a.y * b.y + a.z * b.z + a.w * b.w;
    }
    __shared__ float red[256];
    red[threadIdx.x] = s;
    __syncthreads();
    for (int off = 128; off > 0; off >>= 1) {
        if (threadIdx.x < off) red[threadIdx.x] += red[threadIdx.x + off];
        __syncthreads();
    }
    if (threadIdx.x == 0) {
        float z = red[0] + b_gen[0];
        g_pgen[row] = 1.f / (1.f + expf(-z));
    }
}

// ---------------------------------------------------------------------------
// Kernel 2: bf16 GEMM m16n8k16, 128x256 tile, 3-stage cp.async.
// A = g_xb [m][k], B = g_wt [n][k] (both k-contiguous).
// Epilogue: bias + write logits fp32 + per-row sum(exp).
// ---------------------------------------------------------------------------
__global__ __launch_bounds__(GT, 1)
void gemm_bf16(const float* __restrict__ bias) {
    extern __shared__ __align__(128) char smem[];
    const uint32_t sbase = (uint32_t)__cvta_generic_to_shared(smem);

    const int tid   = threadIdx.x;
    const int lane  = tid & 31;
    const int warp  = tid >> 5;
    const int warpM = warp & 1;       // 0..1 (64 rows)
    const int warpN = warp >> 1;      // 0..3 (64 cols)
    const int g     = lane >> 2;      // 0..7
    const int t     = lane & 3;       // 0..3
    const int m0    = blockIdx.x * BM;
    const int n0    = blockIdx.y * BN;

    // bias preload
    *(float*)(smem + SM_BIAS + tid * 4) = bias[n0 + tid];

    float acc[4][8][4];
#pragma unroll
    for (int i = 0; i < 4; i++)
#pragma unroll
        for (int j = 0; j < 8; j++)
#pragma unroll
            for (int k = 0; k < 4; k++) acc[i][j][k] = 0.f;

    // stage loader: A 512 cp16 (2/thread), B 1024 cp16 (4/thread)
    auto load_stage = [&](int ch, int st) {
        const int kg = ch * BK;
        const uint32_t abuf = sbase + SM_ST0 + st * STAGE_BYTES;
        const uint32_t bbuf = abuf + A_BYTES;
#pragma unroll
        for (int i = 0; i < 2; i++) {
            int s = tid + i * 256;
            int r = s >> 2, c = s & 3;        // row 0..127, 16B chunk 0..3
            int gr = m0 + r;
            if (gr >= MTOT) gr = MTOT - 1;
            cp_async16(abuf + r * 80 + c * 16, g_xb + (size_t)gr * HH + kg + c * 8);
        }
#pragma unroll
        for (int i = 0; i < 4; i++) {
            int s = tid + i * 256;
            int n = s >> 2, c = s & 3;        // row 0..255
            cp_async16(bbuf + n * 80 + c * 16, g_wt + (size_t)(n0 + n) * HH + kg + c * 8);
        }
        cp_commit();
    };

    load_stage(0, 0);
    load_stage(1, 1);

    for (int ch = 0; ch < NCH; ch++) {
        if (ch + 2 < NCH) load_stage(ch + 2, (ch + 2) % STAGES);
        else cp_commit();       // keep group count moving for the tail
        cp_wait<2>();
        __syncthreads();

        const int st = ch % STAGES;
        const uint32_t* Aw = (const uint32_t*)(smem + SM_ST0 + st * STAGE_BYTES)
                             + (warpM * 64) * APITCH_W;
        const uint32_t* Bw = (const uint32_t*)(smem + SM_ST0 + st * STAGE_BYTES + A_BYTES)
                             + (warpN * 64) * APITCH_W;

#pragma unroll
        for (int h = 0; h < 2; h++) {     // two k16 halves per BK=32
            unsigned a[4][4];
#pragma unroll
            for (int mi = 0; mi < 4; mi++) {
                const uint32_t* ap = Aw + (mi * 16 + g) * APITCH_W + h * 8 + t;
                a[mi][0] = ap[0];
                a[mi][1] = ap[8 * APITCH_W];
                a[mi][2] = ap[4];
                a[mi][3] = ap[8 * APITCH_W + 4];
            }
#pragma unroll
            for (int ni = 0; ni < 8; ni++) {
                const uint32_t* bp = Bw + (ni * 8 + g) * APITCH_W + h * 8 + t;
                unsigned b0 = bp[0];
                unsigned b1 = bp[4];
#pragma unroll
                for (int mi = 0; mi < 4; mi++) {
                    asm volatile(
                        "mma.sync.aligned.m16n8k16.row.col.f32.bf16.bf16.f32 "
                        "{%0,%1,%2,%3}, {%4,%5,%6,%7}, {%8,%9}, {%0,%1,%2,%3};"
                        : "+f"(acc[mi][ni][0]), "+f"(acc[mi][ni][1]),
                          "+f"(acc[mi][ni][2]), "+f"(acc[mi][ni][3])
                        : "r"(a[mi][0]), "r"(a[mi][1]), "r"(a[mi][2]), "r"(a[mi][3]),
                          "r"(b0), "r"(b1));
                }
            }
        }
        __syncthreads();
    }

    // Epilogue: bias + write logits + per-row sum of exp
    const float* sb = (const float*)(smem + SM_BIAS);
    float psum_lo[4] = {0.f, 0.f, 0.f, 0.f};
    float psum_hi[4] = {0.f, 0.f, 0.f, 0.f};
#pragma unroll
    for (int ni = 0; ni < 8; ni++) {
        int cl = warpN * 64 + ni * 8 + 2 * t;
        int c  = n0 + cl;
        float b0 = sb[cl], b1 = sb[cl + 1];
#pragma unroll
        for (int mi = 0; mi < 4; mi++) {
            int r = m0 + warpM * 64 + mi * 16 + g;
            float l0 = acc[mi][ni][0] + b0, l1 = acc[mi][ni][1] + b1;
            float l2 = acc[mi][ni][2] + b0, l3 = acc[mi][ni][3] + b1;
            if (r < MTOT) {
                *reinterpret_cast<float2*>(g_logits + (size_t)r * VV + c) =
                    make_float2(l0, l1);
                psum_lo[mi] += __expf(l0) + __expf(l1);
            }
            if (r + 8 < MTOT) {
                *reinterpret_cast<float2*>(g_logits + (size_t)(r + 8) * VV + c) =
                    make_float2(l2, l3);
                psum_hi[mi] += __expf(l2) + __expf(l3);
            }
        }
    }
    __syncthreads();
    float* srow = (float*)smem;   // reuse as [BM] row partials
    if (tid < BM) srow[tid] = 0.f;
    __syncthreads();
#pragma unroll
    for (int mi = 0; mi < 4; mi++) {
        atomicAdd(&srow[warpM * 64 + mi * 16 + g], psum_lo[mi]);
        atomicAdd(&srow[warpM * 64 + mi * 16 + 8 + g], psum_hi[mi]);
    }
    __syncthreads();
    if (tid < BM && m0 + tid < MTOT) atomicAdd(&g_rsum[m0 + tid], srow[tid]);
}

// ---------------------------------------------------------------------------
// Kernel 3: g_C[r] = log(p_gen / sum_exp)
// ---------------------------------------------------------------------------
__global__ void prep_kernel() {
    int r = blockIdx.x * 256 + threadIdx.x;
    if (r < MTOT) g_C[r] = logf(g_pgen[r] / g_rsum[r]);
}

// ---------------------------------------------------------------------------
// Kernel 4: dense pass — out[row, v] = logit[row, v] + C[row]
// ---------------------------------------------------------------------------
__global__ void dense_kernel(float* __restrict__ out) {
    int row = blockIdx.y;
    float C = g_C[row];
    const float4* l4 = (const float4*)(g_logits + (size_t)row * VV);
    float4* o4 = (float4*)(out + (size_t)row * VV);
    int j = blockIdx.x * 256 + threadIdx.x;
#pragma unroll
    for (int k = 0; k < 4; k++) {
        int i = j + k * 2048;
        if (i < V4) {
            float4 l = l4[i];
            l.x += C; l.y += C; l.z += C; l.w += C;
            o4[i] = l;
        }
    }
}

// ---------------------------------------------------------------------------
// Kernel 5: sparse fixup for copy-touched slots (dedup via leader scan)
// ---------------------------------------------------------------------------
__global__ void fixup_kernel(const float* __restrict__ attn,
                             const int* __restrict__ enc,
                             float* __restrict__ out) {
    int row = blockIdx.x;
    int b   = row / TT;
    const float* ar = attn + (size_t)row * LL;

    __shared__ float av[LL];
    __shared__ float sval[LL];
    __shared__ int   sidx[LL];
    __shared__ float red[128];

    int tid = threadIdx.x;

    float m = -1e30f;
    for (int l = tid; l < LL; l += 128) {
        float a = ar[l];
        av[l] = a;
        m = fmaxf(m, a);
    }
    red[tid] = m;
    __syncthreads();
    for (int off = 64; off > 0; off >>= 1) {
        if (tid < off) red[tid] = fmaxf(red[tid], red[tid + off]);
        __syncthreads();
    }
    m = red[0];
    __syncthreads();

    float s = 0.f;
    for (int l = tid; l < LL; l += 128) s += __expf(av[l] - m);
    red[tid] = s;
    __syncthreads();
    for (int off = 64; off > 0; off >>= 1) {
        if (tid < off) red[tid] += red[tid + off];
        __syncthreads();
    }
    s = red[0];

    float scale = (1.f - g_pgen[row]) / s;
    for (int l = tid; l < LL; l += 128) {
        sval[l] = scale * __expf(av[l] - m);
        sidx[l] = enc[b * LL + l];
    }
    __syncthreads();

    for (int l = tid; l < LL; l += 128) {
        int id = sidx[l];
        bool leader = true;
        for (int j = 0; j < l; j++)
            if (sidx[j] == id) { leader = false; break; }
        if (leader) {
            float c = sval[l];
            for (int j = l + 1; j < LL; j++)
                if (sidx[j] == id) c += sval[j];
            size_t o = (size_t)row * VV + id;
            out[o] = logf(c + __expf(out[o]));
        }
    }
}

// ---------------------------------------------------------------------------
extern "C" void kernel_launch(void* const* d_in, const int* in_sizes, int n_in,
                              void* d_out, int out_size) {
    const float* x    = (const float*)d_in[0];
    const float* attn = (const float*)d_in[1];
    const int*   enc  = (const int*)  d_in[2];
    const float* Wv   = (const float*)d_in[3];
    const float* bv   = (const float*)d_in[4];
    const float* wg   = (const float*)d_in[5];
    const float* bg   = (const float*)d_in[6];
    float* out = (float*)d_out;

    static bool attr_set = false;
    if (!attr_set) {
        cudaFuncSetAttribute(gemm_bf16, cudaFuncAttributeMaxDynamicSharedMemorySize,
                             SM_TOTAL);
        attr_set = true;
    }

    convx_kernel<<<(MTOT * HH / 4 + 255) / 256, 256>>>(x);
    dim3 tgrid(VV / 64, HH / 64);          // (500, 16)
    transw_kernel<<<tgrid, 256>>>(Wv);

    pgen_kernel<<<MTOT, 256>>>(x, wg, bg);

    dim3 ggrid((MTOT + BM - 1) / BM, VV / BN);   // (7, 125), m fastest
    gemm_bf16<<<ggrid, GT, SM_TOTAL>>>(bv);

    prep_kernel<<<4, 256>>>();

    dim3 dgrid(8, MTOT);
    dense_kernel<<<dgrid, 256>>>(out);

    fixup_kernel<<<MTOT, 128>>>(attn, enc, out);
}

// round 7
// speedup vs baseline: 3.8869x; 3.5625x over previous
#include <cuda_runtime.h>
#include <cuda_bf16.h>
#include <math.h>
#include <stdint.h>

#define BB   8
#define TT   100
#define MTOT 800
#define HH   1024
#define LL   512
#define VV   32000
#define V4   (VV / 4)

// bf16 GEMM tiling: 128x256 CTA tile, 8 warps (2m x 4n), warp tile 64x64
#define BM 128
#define BN 256
#define BK 32
#define NCH (HH / BK)      // 32
#define GT 256
#define STAGES 3

// smem: bias [0,1024), then 3 stages of (A bf16 10240B + B fp32 33280B)
#define APITCH_W 20                         // A words (40 bf16 = 80 B rows)
#define BPITCH   260                        // B floats per k-row (256 + 4 pad)
#define A_BYTES (BM * 80)                   // 10240
#define B_BYTES (BK * BPITCH * 4)           // 33280
#define STAGE_BYTES (A_BYTES + B_BYTES)     // 43520
#define SM_BIAS 0
#define SM_ST0  1024
#define SM_TOTAL (SM_ST0 + STAGES * STAGE_BYTES)   // 131584

// Scratch (no cudaMalloc allowed)
__device__ float g_logits[(size_t)MTOT * VV];          // 102.4 MB
__device__ __nv_bfloat16 g_xb[(size_t)MTOT * HH];      // 1.6 MB
__device__ float g_pgen[MTOT];
__device__ float g_rsum[MTOT];
__device__ float g_scale[MTOT];

// ---------------------------------------------------------------------------
__device__ __forceinline__ void cp_async16(uint32_t saddr, const void* gsrc) {
    asm volatile("cp.async.cg.shared.global [%0], [%1], 16;\n" ::"r"(saddr), "l"(gsrc));
}
__device__ __forceinline__ void cp_commit() { asm volatile("cp.async.commit_group;\n"); }
template <int N>
__device__ __forceinline__ void cp_wait() {
    asm volatile("cp.async.wait_group %0;\n" ::"n"(N));
}
__device__ __forceinline__ unsigned pack_bf16x2(float lo, float hi) {
    unsigned r;
    asm("cvt.rn.bf16x2.f32 %0, %1, %2;" : "=r"(r) : "f"(hi), "f"(lo));
    return r;
}

// ---------------------------------------------------------------------------
// Kernel 0: convert x -> bf16 (k-contiguous already)
// ---------------------------------------------------------------------------
__global__ void convx_kernel(const float* __restrict__ x) {
    int i = blockIdx.x * 256 + threadIdx.x;       // over float4, 204800 total
    const float4* x4 = (const float4*)x;
    if (i < MTOT * HH / 4) {
        float4 v = x4[i];
        __nv_bfloat162* o = (__nv_bfloat162*)g_xb + i * 2;
        o[0] = __floats2bfloat162_rn(v.x, v.y);
        o[1] = __floats2bfloat162_rn(v.z, v.w);
    }
}

// ---------------------------------------------------------------------------
// Kernel 1: p_gen (fp32) + zero rsum
// ---------------------------------------------------------------------------
__global__ void pgen_kernel(const float* __restrict__ x,
                            const float* __restrict__ w_gen,
                            const float* __restrict__ b_gen) {
    int row = blockIdx.x;
    if (threadIdx.x == 0) g_rsum[row] = 0.f;
    const float4* xr = (const float4*)(x + (size_t)row * HH);
    const float4* wr = (const float4*)w_gen;
    float s = 0.f;
    for (int i = threadIdx.x; i < HH / 4; i += 256) {
        float4 a = xr[i], b = wr[i];
        s += a.x * b.x + a.y * b.y + a.z * b.z + a.w * b.w;
    }
    __shared__ float red[256];
    red[threadIdx.x] = s;
    __syncthreads();
    for (int off = 128; off > 0; off >>= 1) {
        if (threadIdx.x < off) red[threadIdx.x] += red[threadIdx.x + off];
        __syncthreads();
    }
    if (threadIdx.x == 0) {
        float z = red[0] + b_gen[0];
        g_pgen[row] = 1.f / (1.f + expf(-z));
    }
}

// ---------------------------------------------------------------------------
// Kernel 2: bf16 GEMM m16n8k16. A from g_xb (bf16, [m][k]); B from W fp32
// [k][n] smem tiles, fragments packed to bf16x2 on the fly.
// Epilogue: bias + write logits fp32 + per-row sum(exp).
// ---------------------------------------------------------------------------
__global__ __launch_bounds__(GT, 1)
void gemm_bf16(const float* __restrict__ W, const float* __restrict__ bias) {
    extern __shared__ __align__(128) char smem[];
    const uint32_t sbase = (uint32_t)__cvta_generic_to_shared(smem);

    const int tid   = threadIdx.x;
    const int lane  = tid & 31;
    const int warp  = tid >> 5;
    const int warpM = warp & 1;       // 0..1 (64 rows)
    const int warpN = warp >> 1;      // 0..3 (64 cols)
    const int g     = lane >> 2;      // 0..7
    const int t     = lane & 3;       // 0..3
    const int m0    = blockIdx.x * BM;
    const int n0    = blockIdx.y * BN;

    *(float*)(smem + SM_BIAS + tid * 4) = bias[n0 + tid];

    float acc[4][8][4];
#pragma unroll
    for (int i = 0; i < 4; i++)
#pragma unroll
        for (int j = 0; j < 8; j++)
#pragma unroll
            for (int k = 0; k < 4; k++) acc[i][j][k] = 0.f;

    // A: 512 cp16 (2/thread) from g_xb. B: 2048 cp16 (8/thread) from W fp32.
    auto load_stage = [&](int ch, int st) {
        const int kg = ch * BK;
        const uint32_t abuf = sbase + SM_ST0 + st * STAGE_BYTES;
        const uint32_t bbuf = abuf + A_BYTES;
#pragma unroll
        for (int i = 0; i < 2; i++) {
            int s = tid + i * 256;
            int r = s >> 2, c = s & 3;        // row 0..127, 16B chunk 0..3
            int gr = m0 + r;
            if (gr >= MTOT) gr = MTOT - 1;
            cp_async16(abuf + r * 80 + c * 16, g_xb + (size_t)gr * HH + kg + c * 8);
        }
#pragma unroll
        for (int i = 0; i < 8; i++) {
            int s = tid + i * 256;
            int k = s >> 6, c4 = s & 63;      // k-row 0..31, 16B chunk 0..63
            cp_async16(bbuf + k * (BPITCH * 4) + c4 * 16,
                       W + (size_t)(kg + k) * VV + n0 + c4 * 4);
        }
        cp_commit();
    };

    load_stage(0, 0);
    load_stage(1, 1);

    for (int ch = 0; ch < NCH; ch++) {
        if (ch + 2 < NCH) load_stage(ch + 2, (ch + 2) % STAGES);
        else cp_commit();
        cp_wait<2>();
        __syncthreads();

        const int st = ch % STAGES;
        const uint32_t* Aw = (const uint32_t*)(smem + SM_ST0 + st * STAGE_BYTES)
                             + (warpM * 64) * APITCH_W;
        const float* Bf = (const float*)(smem + SM_ST0 + st * STAGE_BYTES + A_BYTES)
                          + warpN * 64;

#pragma unroll
        for (int h = 0; h < 2; h++) {     // two k16 halves per BK=32
            unsigned a[4][4];
#pragma unroll
            for (int mi = 0; mi < 4; mi++) {
                const uint32_t* ap = Aw + (mi * 16 + g) * APITCH_W + h * 8 + t;
                a[mi][0] = ap[0];
                a[mi][1] = ap[8 * APITCH_W];
                a[mi][2] = ap[4];
                a[mi][3] = ap[8 * APITCH_W + 4];
            }
            const float* Bh = Bf + (h * 16 + 2 * t) * BPITCH + g;
#pragma unroll
            for (int ni = 0; ni < 8; ni++) {
                const float* bp = Bh + ni * 8;
                unsigned b0 = pack_bf16x2(bp[0], bp[BPITCH]);
                unsigned b1 = pack_bf16x2(bp[8 * BPITCH], bp[9 * BPITCH]);
#pragma unroll
                for (int mi = 0; mi < 4; mi++) {
                    asm volatile(
                        "mma.sync.aligned.m16n8k16.row.col.f32.bf16.bf16.f32 "
                        "{%0,%1,%2,%3}, {%4,%5,%6,%7}, {%8,%9}, {%0,%1,%2,%3};"
                        : "+f"(acc[mi][ni][0]), "+f"(acc[mi][ni][1]),
                          "+f"(acc[mi][ni][2]), "+f"(acc[mi][ni][3])
                        : "r"(a[mi][0]), "r"(a[mi][1]), "r"(a[mi][2]), "r"(a[mi][3]),
                          "r"(b0), "r"(b1));
                }
            }
        }
        __syncthreads();
    }

    // Epilogue: bias + write logits + per-row sum of exp
    const float* sb = (const float*)(smem + SM_BIAS);
    float psum_lo[4] = {0.f, 0.f, 0.f, 0.f};
    float psum_hi[4] = {0.f, 0.f, 0.f, 0.f};
#pragma unroll
    for (int ni = 0; ni < 8; ni++) {
        int cl = warpN * 64 + ni * 8 + 2 * t;
        int c  = n0 + cl;
        float b0 = sb[cl], b1 = sb[cl + 1];
#pragma unroll
        for (int mi = 0; mi < 4; mi++) {
            int r = m0 + warpM * 64 + mi * 16 + g;
            float l0 = acc[mi][ni][0] + b0, l1 = acc[mi][ni][1] + b1;
            float l2 = acc[mi][ni][2] + b0, l3 = acc[mi][ni][3] + b1;
            if (r < MTOT) {
                *reinterpret_cast<float2*>(g_logits + (size_t)r * VV + c) =
                    make_float2(l0, l1);
                psum_lo[mi] += __expf(l0) + __expf(l1);
            }
            if (r + 8 < MTOT) {
                *reinterpret_cast<float2*>(g_logits + (size_t)(r + 8) * VV + c) =
                    make_float2(l2, l3);
                psum_hi[mi] += __expf(l2) + __expf(l3);
            }
        }
    }
    __syncthreads();
    float* srow = (float*)smem;   // reuse as [BM] row partials
    if (tid < BM) srow[tid] = 0.f;
    __syncthreads();
#pragma unroll
    for (int mi = 0; mi < 4; mi++) {
        atomicAdd(&srow[warpM * 64 + mi * 16 + g], psum_lo[mi]);
        atomicAdd(&srow[warpM * 64 + mi * 16 + 8 + g], psum_hi[mi]);
    }
    __syncthreads();
    if (tid < BM && m0 + tid < MTOT) atomicAdd(&g_rsum[m0 + tid], srow[tid]);
}

// ---------------------------------------------------------------------------
// Kernel 3: g_scale[r] = p_gen / sum_exp  (linear space)
// ---------------------------------------------------------------------------
__global__ void prep_kernel() {
    int r = blockIdx.x * 256 + threadIdx.x;
    if (r < MTOT) g_scale[r] = g_pgen[r] / g_rsum[r];
}

// ---------------------------------------------------------------------------
// Kernel 4: zero row slice of out, then scatter copy-dist (atomicAdd).
//   out[row, enc[b, l]] += (1 - p_gen[row]) * softmax(attn[row])[l]
// (R2-proven structure, measured 23.5us)
// ---------------------------------------------------------------------------
__global__ void scatter_kernel(const float* __restrict__ attn,
                               const int* __restrict__ enc,
                               float* __restrict__ out) {
    int row = blockIdx.x;
    int b   = row / TT;
    const float* ar = attn + (size_t)row * LL;

    float4* o4 = (float4*)(out + (size_t)row * VV);
    float4 z = make_float4(0.f, 0.f, 0.f, 0.f);
    for (int i = threadIdx.x; i < V4; i += 256) o4[i] = z;

    __shared__ float av[LL];
    __shared__ float red[256];

    float m = -1e30f;
    for (int l = threadIdx.x; l < LL; l += 256) {
        float a = ar[l];
        av[l] = a;
        m = fmaxf(m, a);
    }
    red[threadIdx.x] = m;
    __syncthreads();
    for (int off = 128; off > 0; off >>= 1) {
        if (threadIdx.x < off)
            red[threadIdx.x] = fmaxf(red[threadIdx.x], red[threadIdx.x + off]);
        __syncthreads();
    }
    m = red[0];
    __syncthreads();

    float s = 0.f;
    for (int l = threadIdx.x; l < LL; l += 256) s += __expf(av[l] - m);
    red[threadIdx.x] = s;
    __syncthreads();
    for (int off = 128; off > 0; off >>= 1) {
        if (threadIdx.x < off) red[threadIdx.x] += red[threadIdx.x + off];
        __syncthreads();
    }
    s = red[0];

    float scale = (1.f - g_pgen[row]) / s;
    for (int l = threadIdx.x; l < LL; l += 256) {
        float val = scale * __expf(av[l] - m);
        int idx = enc[b * LL + l];
        atomicAdd(&out[(size_t)row * VV + idx], val);
    }
}

// ---------------------------------------------------------------------------
// Kernel 5: final — out = log(out_copy + scale[row] * exp(logit))
// ---------------------------------------------------------------------------
__global__ void final_kernel(float* __restrict__ out) {
    int row = blockIdx.y;
    float sc = g_scale[row];
    const float4* l4 = (const float4*)(g_logits + (size_t)row * VV);
    float4* o4 = (float4*)(out + (size_t)row * VV);
    int j = blockIdx.x * 256 + threadIdx.x;
#pragma unroll
    for (int k = 0; k < 4; k++) {
        int i = j + k * 2048;
        if (i < V4) {
            float4 l = l4[i];
            float4 o = o4[i];
            o.x = __logf(o.x + sc * __expf(l.x));
            o.y = __logf(o.y + sc * __expf(l.y));
            o.z = __logf(o.z + sc * __expf(l.z));
            o.w = __logf(o.w + sc * __expf(l.w));
            o4[i] = o;
        }
    }
}

// ---------------------------------------------------------------------------
extern "C" void kernel_launch(void* const* d_in, const int* in_sizes, int n_in,
                              void* d_out, int out_size) {
    const float* x    = (const float*)d_in[0];
    const float* attn = (const float*)d_in[1];
    const int*   enc  = (const int*)  d_in[2];
    const float* Wv   = (const float*)d_in[3];
    const float* bv   = (const float*)d_in[4];
    const float* wg   = (const float*)d_in[5];
    const float* bg   = (const float*)d_in[6];
    float* out = (float*)d_out;

    static bool attr_set = false;
    if (!attr_set) {
        cudaFuncSetAttribute(gemm_bf16, cudaFuncAttributeMaxDynamicSharedMemorySize,
                             SM_TOTAL);
        attr_set = true;
    }

    convx_kernel<<<(MTOT * HH / 4 + 255) / 256, 256>>>(x);
    pgen_kernel<<<MTOT, 256>>>(x, wg, bg);

    dim3 ggrid((MTOT + BM - 1) / BM, VV / BN);   // (7, 125), m fastest
    gemm_bf16<<<ggrid, GT, SM_TOTAL>>>(Wv, bv);

    prep_kernel<<<4, 256>>>();

    scatter_kernel<<<MTOT, 256>>>(attn, enc, out);

    dim3 fgrid(8, MTOT);
    final_kernel<<<fgrid, 256>>>(out);
}